// round 2
// baseline (speedup 1.0000x reference)
#include <cuda_runtime.h>

#define N_NODES 100000
#define E_EDGES 1200000
#define F 64

// ---------------- scratch (device globals; no allocation allowed) ----------
__device__ int   g_is64;
__device__ int   g_cnt[N_NODES];
__device__ int   g_cur[N_NODES];
__device__ int   g_off[N_NODES + 1];
__device__ int   g_srcs[E_EDGES];
__device__ __align__(16) float g_agg[N_NODES * F];
__device__ __align__(16) float g_hbuf[2][N_NODES * F];

// ---------------- dtype detection ------------------------------------------
// If edge_index is int64 (values < 2^31, little-endian), all odd int32 words
// of the buffer are zero. If int32, odd words are random node ids (≠ all 0).
__global__ void detect_kernel(const int* __restrict__ ei32) {
    __shared__ int any;
    if (threadIdx.x == 0) any = 0;
    __syncthreads();
    int acc = 0;
    for (int i = threadIdx.x * 2 + 1; i < 4096; i += 2 * blockDim.x)
        acc |= ei32[i];
    if (acc) atomicOr(&any, 1);
    __syncthreads();
    if (threadIdx.x == 0) g_is64 = (any == 0) ? 1 : 0;
}

__device__ __forceinline__ int load_idx(const void* ei, long long pos, bool is64) {
    if (is64) return (int)((const long long*)ei)[pos];
    return ((const int*)ei)[pos];
}

// ---------------- CSR build -------------------------------------------------
__global__ void zero_kernel() {
    int i = blockIdx.x * blockDim.x + threadIdx.x;
    if (i < N_NODES) { g_cnt[i] = 0; g_cur[i] = 0; }
}

__global__ void count_kernel(const void* __restrict__ ei) {
    const bool is64 = (g_is64 != 0);
    int stride = gridDim.x * blockDim.x;
    for (int e = blockIdx.x * blockDim.x + threadIdx.x; e < E_EDGES; e += stride) {
        int d = load_idx(ei, (long long)E_EDGES + e, is64);
        if ((unsigned)d < (unsigned)N_NODES)
            atomicAdd(&g_cnt[d], 1);
    }
}

__global__ void scan_kernel() {
    __shared__ int tot[1024];
    const int t = threadIdx.x;
    const int CH = (N_NODES + 1023) / 1024;   // 98
    int lo = t * CH;
    int hi = lo + CH; if (hi > N_NODES) hi = N_NODES;
    int s = 0;
    for (int i = lo; i < hi; i++) s += g_cnt[i];
    tot[t] = s;
    __syncthreads();
    for (int off = 1; off < 1024; off <<= 1) {
        int v = (t >= off) ? tot[t - off] : 0;
        __syncthreads();
        tot[t] += v;
        __syncthreads();
    }
    int run = (t == 0) ? 0 : tot[t - 1];
    for (int i = lo; i < hi; i++) { g_off[i] = run; run += g_cnt[i]; }
    if (t == 1023) g_off[N_NODES] = run;
}

__global__ void fill_kernel(const void* __restrict__ ei) {
    const bool is64 = (g_is64 != 0);
    int stride = gridDim.x * blockDim.x;
    for (int e = blockIdx.x * blockDim.x + threadIdx.x; e < E_EDGES; e += stride) {
        int d = load_idx(ei, (long long)E_EDGES + e, is64);
        int s = load_idx(ei, (long long)e, is64);
        if ((unsigned)d < (unsigned)N_NODES && (unsigned)s < (unsigned)N_NODES) {
            int p = g_off[d] + atomicAdd(&g_cur[d], 1);
            g_srcs[p] = s;
        }
    }
}

// ---------------- aggregation: one warp per destination node ---------------
__global__ void agg_kernel(const float* __restrict__ x, int hin_sel) {
    const float* __restrict__ h = (hin_sel < 0) ? x : g_hbuf[hin_sel];
    int w = (blockIdx.x * blockDim.x + threadIdx.x) >> 5;
    int lane = threadIdx.x & 31;
    if (w >= N_NODES) return;
    float a0 = 0.f, a1 = 0.f;
    int p0 = g_off[w], p1 = g_off[w + 1];
    for (int p = p0; p < p1; p++) {
        int s = g_srcs[p];
        const float* r = h + (size_t)s * F;
        a0 += r[lane];
        a1 += r[lane + 32];
    }
    g_agg[(size_t)w * F + lane]      = a0;
    g_agg[(size_t)w * F + lane + 32] = a1;
}

// ---------------- fused dual-GEMM + bias (+tanh) ----------------------------
__device__ __forceinline__ float fast_tanh(float x) {
    float e = __expf(2.f * x);           // saturates to 0 / inf correctly
    return 1.f - 2.f / (e + 1.f);
}

// out[i,f] = sum_k agg[i,k]*Wl[f,k] + sum_k h[i,k]*Wr[f,k] + bl[f]
// tile: 32 nodes x 64 outputs per block (128 threads), 4x4 micro-tile.
__global__ void lin_kernel(const float* __restrict__ x, int hin_sel, int hout_sel,
                           float* __restrict__ dout,
                           const float* __restrict__ Wl, const float* __restrict__ bl,
                           const float* __restrict__ Wr, int do_tanh) {
    __shared__ float wls[64 * 64];   // wls[k*64 + ((f+k)&63)] = Wl[f*64+k]
    __shared__ float wrs[64 * 64];
    __shared__ float as_[32 * 64];   // as_[node*64 + ((k + node*4)&63)]
    __shared__ float hs_[32 * 64];

    const float* __restrict__ hin = (hin_sel < 0) ? x : g_hbuf[hin_sel];
    float* __restrict__ hout = (hout_sel < 0) ? dout : g_hbuf[hout_sel];

    for (int idx = threadIdx.x; idx < 64 * 64; idx += blockDim.x) {
        int f = idx >> 6, k = idx & 63;
        int sidx = k * 64 + ((f + k) & 63);
        wls[sidx] = Wl[idx];
        wrs[sidx] = Wr[idx];
    }

    const int fx = threadIdx.x & 15;   // f = fx*4 + j
    const int ny = threadIdx.x >> 4;   // nodes ny*4 + n
    const int f0 = fx * 4;
    const float b0 = bl[f0 + 0], b1 = bl[f0 + 1], b2 = bl[f0 + 2], b3 = bl[f0 + 3];

    const int NTILES = N_NODES / 32;   // 3125 exactly
    for (int tile = blockIdx.x; tile < NTILES; tile += gridDim.x) {
        int base = tile * 32;
        __syncthreads();
        for (int v = threadIdx.x; v < 32 * 16; v += blockDim.x) {
            int node = v >> 4, kq = v & 15;
            const float4 va = ((const float4*)(g_agg + (size_t)(base + node) * 64))[kq];
            const float4 vh = ((const float4*)(hin   + (size_t)(base + node) * 64))[kq];
            int nb = node * 64;
            int sw = node * 4;
            int k0 = kq * 4;
            as_[nb + ((k0 + 0 + sw) & 63)] = va.x;
            as_[nb + ((k0 + 1 + sw) & 63)] = va.y;
            as_[nb + ((k0 + 2 + sw) & 63)] = va.z;
            as_[nb + ((k0 + 3 + sw) & 63)] = va.w;
            hs_[nb + ((k0 + 0 + sw) & 63)] = vh.x;
            hs_[nb + ((k0 + 1 + sw) & 63)] = vh.y;
            hs_[nb + ((k0 + 2 + sw) & 63)] = vh.z;
            hs_[nb + ((k0 + 3 + sw) & 63)] = vh.w;
        }
        __syncthreads();

        float acc[4][4];
        #pragma unroll
        for (int n = 0; n < 4; n++)
            #pragma unroll
            for (int j = 0; j < 4; j++) acc[n][j] = 0.f;

        int nb[4], sw[4];
        #pragma unroll
        for (int n = 0; n < 4; n++) {
            int node = ny * 4 + n;
            nb[n] = node * 64;
            sw[n] = node * 4;
        }

        #pragma unroll
        for (int k = 0; k < 64; k++) {
            const int kb = k * 64;
            const float wl0 = wls[kb + ((f0 + 0 + k) & 63)];
            const float wl1 = wls[kb + ((f0 + 1 + k) & 63)];
            const float wl2 = wls[kb + ((f0 + 2 + k) & 63)];
            const float wl3 = wls[kb + ((f0 + 3 + k) & 63)];
            const float wr0 = wrs[kb + ((f0 + 0 + k) & 63)];
            const float wr1 = wrs[kb + ((f0 + 1 + k) & 63)];
            const float wr2 = wrs[kb + ((f0 + 2 + k) & 63)];
            const float wr3 = wrs[kb + ((f0 + 3 + k) & 63)];
            #pragma unroll
            for (int n = 0; n < 4; n++) {
                const float a  = as_[nb[n] + ((k + sw[n]) & 63)];
                const float hh = hs_[nb[n] + ((k + sw[n]) & 63)];
                acc[n][0] = fmaf(a, wl0, acc[n][0]); acc[n][0] = fmaf(hh, wr0, acc[n][0]);
                acc[n][1] = fmaf(a, wl1, acc[n][1]); acc[n][1] = fmaf(hh, wr1, acc[n][1]);
                acc[n][2] = fmaf(a, wl2, acc[n][2]); acc[n][2] = fmaf(hh, wr2, acc[n][2]);
                acc[n][3] = fmaf(a, wl3, acc[n][3]); acc[n][3] = fmaf(hh, wr3, acc[n][3]);
            }
        }

        #pragma unroll
        for (int n = 0; n < 4; n++) {
            int node = base + ny * 4 + n;
            float v0 = acc[n][0] + b0;
            float v1 = acc[n][1] + b1;
            float v2 = acc[n][2] + b2;
            float v3 = acc[n][3] + b3;
            if (do_tanh) {
                v0 = fast_tanh(v0); v1 = fast_tanh(v1);
                v2 = fast_tanh(v2); v3 = fast_tanh(v3);
            }
            float4 vv = make_float4(v0, v1, v2, v3);
            *(float4*)(hout + (size_t)node * 64 + f0) = vv;
        }
    }
}

// ---------------- launch -----------------------------------------------------
extern "C" void kernel_launch(void* const* d_in, const int* in_sizes, int n_in,
                              void* d_out, int out_size) {
    const float* x      = (const float*)d_in[0];
    const void*  ei     = d_in[1];
    const float* Wl_in  = (const float*)d_in[2];
    const float* bl_in  = (const float*)d_in[3];
    const float* Wr_in  = (const float*)d_in[4];
    const float* Wl_med = (const float*)d_in[5];
    const float* bl_med = (const float*)d_in[6];
    const float* Wr_med = (const float*)d_in[7];
    const float* Wl_out = (const float*)d_in[8];
    const float* bl_out = (const float*)d_in[9];
    const float* Wr_out = (const float*)d_in[10];
    float*       out    = (float*)d_out;

    // CSR build (edge structure shared by all 4 layers)
    detect_kernel<<<1, 256>>>((const int*)ei);
    zero_kernel<<<(N_NODES + 255) / 256, 256>>>();
    count_kernel<<<1024, 256>>>(ei);
    scan_kernel<<<1, 1024>>>();
    fill_kernel<<<1024, 256>>>(ei);

    const int AGG_BLOCKS = (N_NODES * 32 + 255) / 256;  // 1 warp / node
    const int LIN_BLOCKS = 608;                         // grid-stride over 3125 tiles

    // layer 0: x -> hbuf[0] (tanh)
    agg_kernel<<<AGG_BLOCKS, 256>>>(x, -1);
    lin_kernel<<<LIN_BLOCKS, 128>>>(x, -1, 0, nullptr, Wl_in, bl_in, Wr_in, 1);
    // layer 1: hbuf[0] -> hbuf[1] (tanh)
    agg_kernel<<<AGG_BLOCKS, 256>>>(nullptr, 0);
    lin_kernel<<<LIN_BLOCKS, 128>>>(nullptr, 0, 1, nullptr, Wl_med, bl_med, Wr_med, 1);
    // layer 2: hbuf[1] -> hbuf[0] (tanh)
    agg_kernel<<<AGG_BLOCKS, 256>>>(nullptr, 1);
    lin_kernel<<<LIN_BLOCKS, 128>>>(nullptr, 1, 0, nullptr, Wl_med, bl_med, Wr_med, 1);
    // layer 3: hbuf[0] -> d_out (no tanh)
    agg_kernel<<<AGG_BLOCKS, 256>>>(nullptr, 0);
    lin_kernel<<<LIN_BLOCKS, 128>>>(nullptr, 0, -1, out, Wl_out, bl_out, Wr_out, 0);
}

// round 3
// speedup vs baseline: 1.4641x; 1.4641x over previous
#include <cuda_runtime.h>

#define N_NODES 100000
#define E_EDGES 1200000
#define F 64

#define SCAN_BLK 256
#define NPART ((N_NODES + SCAN_BLK - 1) / SCAN_BLK)   // 391

// ---------------- scratch (device globals; no allocation allowed) ----------
__device__ int   g_is64;
__device__ int   g_cnt[N_NODES];
__device__ int   g_cur[N_NODES];
__device__ int   g_off[N_NODES + 1];
__device__ int   g_part[NPART];
__device__ int   g_pscan[NPART];
__device__ int   g_srcs[E_EDGES];
__device__ __align__(16) float g_agg[N_NODES * F];
__device__ __align__(16) float g_hbuf[2][N_NODES * F];

// ---------------- dtype detection ------------------------------------------
// int64 indices (< 2^31, little-endian): all odd int32 words of src are zero.
__global__ void detect_kernel(const int* __restrict__ ei32) {
    __shared__ int any;
    if (threadIdx.x == 0) any = 0;
    __syncthreads();
    int acc = 0;
    for (int i = threadIdx.x * 2 + 1; i < 4096; i += 2 * blockDim.x)
        acc |= ei32[i];
    if (acc) atomicOr(&any, 1);
    __syncthreads();
    if (threadIdx.x == 0) g_is64 = (any == 0) ? 1 : 0;
}

__device__ __forceinline__ int load_idx(const void* ei, long long pos, bool is64) {
    if (is64) return (int)((const long long*)ei)[pos];
    return ((const int*)ei)[pos];
}

// ---------------- CSR build -------------------------------------------------
__global__ void zero_kernel() {
    int i = blockIdx.x * blockDim.x + threadIdx.x;
    if (i < N_NODES) { g_cnt[i] = 0; g_cur[i] = 0; }
}

__global__ void count_kernel(const void* __restrict__ ei) {
    const bool is64 = (g_is64 != 0);
    int stride = gridDim.x * blockDim.x;
    for (int e = blockIdx.x * blockDim.x + threadIdx.x; e < E_EDGES; e += stride) {
        int d = load_idx(ei, (long long)E_EDGES + e, is64);
        if ((unsigned)d < (unsigned)N_NODES)
            atomicAdd(&g_cnt[d], 1);
    }
}

// block partial sums of counts
__global__ void part_sum_kernel() {
    __shared__ int red[SCAN_BLK];
    int i = blockIdx.x * SCAN_BLK + threadIdx.x;
    red[threadIdx.x] = (i < N_NODES) ? g_cnt[i] : 0;
    __syncthreads();
    for (int s = SCAN_BLK / 2; s > 0; s >>= 1) {
        if (threadIdx.x < s) red[threadIdx.x] += red[threadIdx.x + s];
        __syncthreads();
    }
    if (threadIdx.x == 0) g_part[blockIdx.x] = red[0];
}

// single-block scan of NPART partials (exclusive), writes total to g_off[N]
__global__ void part_scan_kernel() {
    __shared__ int s[512];
    int t = threadIdx.x;
    int v = (t < NPART) ? g_part[t] : 0;
    s[t] = v;
    __syncthreads();
    for (int off = 1; off < 512; off <<= 1) {
        int u = (t >= off) ? s[t - off] : 0;
        __syncthreads();
        s[t] += u;
        __syncthreads();
    }
    if (t < NPART) g_pscan[t] = s[t] - v;       // exclusive
    if (t == 511) g_off[N_NODES] = s[511];      // total
}

// per-block exclusive scan + base offset
__global__ void offsets_kernel() {
    __shared__ int s[SCAN_BLK];
    int t = threadIdx.x;
    int i = blockIdx.x * SCAN_BLK + t;
    int v = (i < N_NODES) ? g_cnt[i] : 0;
    s[t] = v;
    __syncthreads();
    for (int off = 1; off < SCAN_BLK; off <<= 1) {
        int u = (t >= off) ? s[t - off] : 0;
        __syncthreads();
        s[t] += u;
        __syncthreads();
    }
    if (i < N_NODES) g_off[i] = g_pscan[blockIdx.x] + s[t] - v;
}

__global__ void fill_kernel(const void* __restrict__ ei) {
    const bool is64 = (g_is64 != 0);
    int stride = gridDim.x * blockDim.x;
    for (int e = blockIdx.x * blockDim.x + threadIdx.x; e < E_EDGES; e += stride) {
        int d = load_idx(ei, (long long)E_EDGES + e, is64);
        int s = load_idx(ei, (long long)e, is64);
        if ((unsigned)d < (unsigned)N_NODES && (unsigned)s < (unsigned)N_NODES) {
            int p = g_off[d] + atomicAdd(&g_cur[d], 1);
            g_srcs[p] = s;
        }
    }
}

// ---------------- aggregation: one warp per destination node ---------------
__global__ void agg_kernel(const float* __restrict__ x, int hin_sel) {
    const float* __restrict__ h = (hin_sel < 0) ? x : g_hbuf[hin_sel];
    int w = (blockIdx.x * blockDim.x + threadIdx.x) >> 5;
    int lane = threadIdx.x & 31;
    if (w >= N_NODES) return;
    float a0 = 0.f, a1 = 0.f;
    int p0 = g_off[w], p1 = g_off[w + 1];
    for (int p = p0; p < p1; p++) {
        int s = g_srcs[p];
        const float* r = h + (size_t)s * F;
        a0 += r[lane];
        a1 += r[lane + 32];
    }
    g_agg[(size_t)w * F + lane]      = a0;
    g_agg[(size_t)w * F + lane + 32] = a1;
}

// ---------------- fused dual-GEMM + bias (+tanh), FFMA2 path ----------------
__device__ __forceinline__ float fast_tanh(float x) {
    float e = __expf(2.f * x);
    return 1.f - 2.f / (e + 1.f);
}

#define LIN_THREADS 128
#define TILE_NODES  128
#define ASTRIDE     65     // act row pad: 8*65 % 32 = 8 -> 4 ny hit 4 distinct banks
#define WSTRIDE     66     // weight row pad: even (float2 align), 2-way STS conflict only
#define LIN_SMEM_FLOATS (2 * 64 * WSTRIDE + 2 * TILE_NODES * ASTRIDE)

__device__ __forceinline__ unsigned long long pack2(float v) {
    unsigned long long r;
    asm("mov.b64 %0, {%1, %1};" : "=l"(r) : "f"(v));
    return r;
}
__device__ __forceinline__ void ffma2(unsigned long long& acc, unsigned long long a,
                                      unsigned long long b) {
    asm("fma.rn.f32x2 %0, %1, %2, %0;" : "+l"(acc) : "l"(a), "l"(b));
}
__device__ __forceinline__ float2 unpack2(unsigned long long v) {
    float lo, hi;
    asm("mov.b64 {%0, %1}, %2;" : "=f"(lo), "=f"(hi) : "l"(v));
    return make_float2(lo, hi);
}

__global__ void __launch_bounds__(LIN_THREADS)
lin_kernel(const float* __restrict__ x, int hin_sel, int hout_sel,
           float* __restrict__ dout,
           const float* __restrict__ Wl, const float* __restrict__ bl,
           const float* __restrict__ Wr, int do_tanh) {
    extern __shared__ float sm[];
    float* wls = sm;                          // [64][WSTRIDE] k-major: wls[k][f]=Wl[f*64+k]
    float* wrs = wls + 64 * WSTRIDE;
    float* as_ = wrs + 64 * WSTRIDE;          // [TILE_NODES][ASTRIDE]
    float* hs_ = as_ + TILE_NODES * ASTRIDE;

    const float* __restrict__ hin = (hin_sel < 0) ? x : g_hbuf[hin_sel];
    float* __restrict__ hout = (hout_sel < 0) ? dout : g_hbuf[hout_sel];

    // weights: coalesced LDG, transposed STS (2-way conflict via pad 66)
    for (int idx = threadIdx.x; idx < 64 * 64; idx += LIN_THREADS) {
        int f = idx >> 6, k = idx & 63;
        wls[k * WSTRIDE + f] = Wl[idx];
        wrs[k * WSTRIDE + f] = Wr[idx];
    }

    const int base = blockIdx.x * TILE_NODES;
    // activations: float4 LDG, scalar STS into padded rows
    for (int v = threadIdx.x; v < TILE_NODES * 16; v += LIN_THREADS) {
        int node = v >> 4, kq = (v & 15) * 4;
        int gn = base + node;
        float4 va = make_float4(0.f, 0.f, 0.f, 0.f);
        float4 vh = va;
        if (gn < N_NODES) {
            va = *(const float4*)(g_agg + (size_t)gn * 64 + kq);
            vh = *(const float4*)(hin   + (size_t)gn * 64 + kq);
        }
        float* ap = as_ + node * ASTRIDE + kq;
        ap[0] = va.x; ap[1] = va.y; ap[2] = va.z; ap[3] = va.w;
        float* hp = hs_ + node * ASTRIDE + kq;
        hp[0] = vh.x; hp[1] = vh.y; hp[2] = vh.z; hp[3] = vh.w;
    }
    __syncthreads();

    const int fx = threadIdx.x & 7;       // 8 output groups of 8
    const int ny = threadIdx.x >> 3;      // 16 node groups of 8
    const int f0 = fx * 8;
    const int n0 = ny * 8;

    unsigned long long acc[8][4];
    #pragma unroll
    for (int n = 0; n < 8; n++)
        #pragma unroll
        for (int jp = 0; jp < 4; jp++) acc[n][jp] = 0ull;

    #pragma unroll 8
    for (int k = 0; k < 64; k++) {
        const unsigned long long* wl64 =
            (const unsigned long long*)(wls + k * WSTRIDE + f0);
        const unsigned long long* wr64 =
            (const unsigned long long*)(wrs + k * WSTRIDE + f0);
        unsigned long long wl[4], wr[4];
        #pragma unroll
        for (int jp = 0; jp < 4; jp++) { wl[jp] = wl64[jp]; wr[jp] = wr64[jp]; }

        const float* ab = as_ + n0 * ASTRIDE + k;
        const float* hb = hs_ + n0 * ASTRIDE + k;
        #pragma unroll
        for (int n = 0; n < 8; n++) {
            unsigned long long a2 = pack2(ab[n * ASTRIDE]);
            unsigned long long h2 = pack2(hb[n * ASTRIDE]);
            #pragma unroll
            for (int jp = 0; jp < 4; jp++) {
                ffma2(acc[n][jp], a2, wl[jp]);
                ffma2(acc[n][jp], h2, wr[jp]);
            }
        }
    }

    float bias[8];
    #pragma unroll
    for (int j = 0; j < 8; j++) bias[j] = bl[f0 + j];

    #pragma unroll
    for (int n = 0; n < 8; n++) {
        int gn = base + n0 + n;
        if (gn >= N_NODES) continue;
        float v[8];
        #pragma unroll
        for (int jp = 0; jp < 4; jp++) {
            float2 p = unpack2(acc[n][jp]);
            v[2 * jp]     = p.x + bias[2 * jp];
            v[2 * jp + 1] = p.y + bias[2 * jp + 1];
        }
        if (do_tanh) {
            #pragma unroll
            for (int j = 0; j < 8; j++) v[j] = fast_tanh(v[j]);
        }
        float* op = hout + (size_t)gn * 64 + f0;
        *(float4*)(op)     = make_float4(v[0], v[1], v[2], v[3]);
        *(float4*)(op + 4) = make_float4(v[4], v[5], v[6], v[7]);
    }
}

// ---------------- launch -----------------------------------------------------
extern "C" void kernel_launch(void* const* d_in, const int* in_sizes, int n_in,
                              void* d_out, int out_size) {
    const float* x      = (const float*)d_in[0];
    const void*  ei     = d_in[1];
    const float* Wl_in  = (const float*)d_in[2];
    const float* bl_in  = (const float*)d_in[3];
    const float* Wr_in  = (const float*)d_in[4];
    const float* Wl_med = (const float*)d_in[5];
    const float* bl_med = (const float*)d_in[6];
    const float* Wr_med = (const float*)d_in[7];
    const float* Wl_out = (const float*)d_in[8];
    const float* bl_out = (const float*)d_in[9];
    const float* Wr_out = (const float*)d_in[10];
    float*       out    = (float*)d_out;

    static int smem_set = 0;
    const int LIN_SMEM = LIN_SMEM_FLOATS * 4;   // 100,352 bytes
    if (!smem_set) {
        cudaFuncSetAttribute(lin_kernel,
                             cudaFuncAttributeMaxDynamicSharedMemorySize, LIN_SMEM);
        smem_set = 1;
    }

    // CSR build
    detect_kernel<<<1, 256>>>((const int*)ei);
    zero_kernel<<<(N_NODES + 255) / 256, 256>>>();
    count_kernel<<<1024, 256>>>(ei);
    part_sum_kernel<<<NPART, SCAN_BLK>>>();
    part_scan_kernel<<<1, 512>>>();
    offsets_kernel<<<NPART, SCAN_BLK>>>();
    fill_kernel<<<1024, 256>>>(ei);

    const int AGG_BLOCKS = (N_NODES * 32 + 255) / 256;      // 1 warp / node
    const int LIN_BLOCKS = (N_NODES + TILE_NODES - 1) / TILE_NODES;  // 782

    // layer 0: x -> hbuf[0] (tanh)
    agg_kernel<<<AGG_BLOCKS, 256>>>(x, -1);
    lin_kernel<<<LIN_BLOCKS, LIN_THREADS, LIN_SMEM>>>(x, -1, 0, nullptr,
                                                      Wl_in, bl_in, Wr_in, 1);
    // layer 1
    agg_kernel<<<AGG_BLOCKS, 256>>>(nullptr, 0);
    lin_kernel<<<LIN_BLOCKS, LIN_THREADS, LIN_SMEM>>>(nullptr, 0, 1, nullptr,
                                                      Wl_med, bl_med, Wr_med, 1);
    // layer 2
    agg_kernel<<<AGG_BLOCKS, 256>>>(nullptr, 1);
    lin_kernel<<<LIN_BLOCKS, LIN_THREADS, LIN_SMEM>>>(nullptr, 1, 0, nullptr,
                                                      Wl_med, bl_med, Wr_med, 1);
    // layer 3: -> d_out (no tanh)
    agg_kernel<<<AGG_BLOCKS, 256>>>(nullptr, 0);
    lin_kernel<<<LIN_BLOCKS, LIN_THREADS, LIN_SMEM>>>(nullptr, 0, -1, out,
                                                      Wl_out, bl_out, Wr_out, 0);
}